// round 14
// baseline (speedup 1.0000x reference)
#include <cuda_runtime.h>
#include <cuda_fp16.h>
#include <cstdint>

// PatchEmbedding, fused fp16 tensor path, 2 kernels:
//   1) round_wh: W -> fp16 Wh [768,704] (K padded 672->704 with zeros)
//   2) gemm:     D = gather(x) * Wh^T + bias. A is gathered from x INSIDE the
//      GEMM (LDG fp32 -> cvt fp16 -> STS, swizzled), interleaved with MMA
//      s-steps; B via cp.async 3-stage. mma.m16n8k16.f16, BM=128 x BN=128,
//      256 thr (8 warps, 2Mx4N), warp tile 64x32, fragment double-buffering.

namespace {

constexpr int C_   = 4;
constexpr int Himg = 420;
constexpr int Wimg = 312;
constexpr int PH   = 14;
constexpr int PW   = 12;
constexpr int GW   = 26;
constexpr int E    = 768;
constexpr int NV   = 390;
constexpr int K    = 672;
constexpr int Kp   = 704;            // padded K (multiple of 64)
constexpr int Kp4  = Kp / 4;         // 176
constexpr int K4   = K / 4;          // 168 valid float4-groups per row
constexpr int M    = 96 * NV;        // 37440
constexpr int HW_  = Himg * Wimg;
constexpr int CHW  = C_ * HW_;

constexpr int BM = 128, BN = 128, BK = 64;   // BK in fp16 elements (128 B)
constexpr int NKT    = Kp / BK;              // 11
constexpr int NBLK   = E / BN;               // 6
constexpr int MBLK   = (M + BM - 1) / BM;    // 293
constexpr int STAGES = 3;
constexpr int A_BYTES = BM * BK * 2;               // 16 KB
constexpr int STAGE_BYTES = (BM + BN) * BK * 2;    // 32 KB
constexpr int SM_KOFF  = STAGES * STAGE_BYTES;     // koff table after stages
constexpr int SM_TOTAL = SM_KOFF + K4 * 4;         // 96 KB + 672 B

constexpr int NW4 = E * Kp4;         // W half4-groups

} // namespace

// scratch (module-scope device global; allocation-free at launch time)
__device__ __align__(16) __half g_Wh[(size_t)E * Kp];   // ~1.1 MB

namespace {

__device__ __forceinline__ uint32_t smem_u32(const void* p) {
    uint32_t a;
    asm("{ .reg .u64 t; cvta.to.shared.u64 t, %1; cvt.u32.u64 %0, t; }"
        : "=r"(a) : "l"(p));
    return a;
}

__device__ __forceinline__ void cp16(uint32_t dst, const void* src) {
    asm volatile("cp.async.cg.shared.global [%0], [%1], 16;"
                 :: "r"(dst), "l"(src) : "memory");
}

__device__ __forceinline__ void ldsm_x4(uint32_t r[4], uint32_t addr) {
    asm volatile("ldmatrix.sync.aligned.m8n8.x4.shared.b16 {%0,%1,%2,%3}, [%4];"
                 : "=r"(r[0]), "=r"(r[1]), "=r"(r[2]), "=r"(r[3]) : "r"(addr));
}

__device__ __forceinline__ void mma_f16(float d[4], const uint32_t a[4],
                                        uint32_t b0, uint32_t b1) {
    asm volatile(
        "mma.sync.aligned.m16n8k16.row.col.f32.f16.f16.f32 "
        "{%0,%1,%2,%3}, {%4,%5,%6,%7}, {%8,%9}, {%0,%1,%2,%3};"
        : "+f"(d[0]), "+f"(d[1]), "+f"(d[2]), "+f"(d[3])
        : "r"(a[0]), "r"(a[1]), "r"(a[2]), "r"(a[3]), "r"(b0), "r"(b1));
}

__device__ __forceinline__ uint2 pack4(float4 v) {
    __half2 lo = __floats2half2_rn(v.x, v.y);
    __half2 hi = __floats2half2_rn(v.z, v.w);
    uint2 r;
    r.x = *reinterpret_cast<uint32_t*>(&lo);
    r.y = *reinterpret_cast<uint32_t*>(&hi);
    return r;
}

// ---- pre-pass: W -> fp16, padded to Kp ----
__global__ void round_wh(const float* __restrict__ Wm) {
    int idx = blockIdx.x * blockDim.x + threadIdx.x;   // half4-group id
    if (idx >= NW4) return;
    int e = idx / Kp4;
    int t = idx - e * Kp4;
    uint2 val = make_uint2(0, 0);
    if (t < K4)
        val = pack4(*reinterpret_cast<const float4*>(Wm + (size_t)e * K + t * 4));
    *reinterpret_cast<uint2*>(g_Wh + (size_t)e * Kp + t * 4) = val;
}

// ---- fused GEMM: 256 threads, 8 warps (2M x 4N), warp tile 64x32 ----
__global__ __launch_bounds__(256, 2)
void patch_embed_gemm(const float* __restrict__ x,
                      const float* __restrict__ bias,
                      const int*   __restrict__ valid,
                      float*       __restrict__ out)
{
    extern __shared__ char smem[];
    const uint32_t sb = smem_u32(smem);
    int* koff_s = reinterpret_cast<int*>(smem + SM_KOFF);

    const int tid  = threadIdx.x;
    const int lane = tid & 31;
    const int wid  = tid >> 5;

    const int bid = blockIdx.x;
    const int n0  = (bid % NBLK) * BN;   // n innermost -> x/A panel L2 reuse
    const int m0  = (bid / NBLK) * BM;

    // ---- koff table: float4-group g -> float offset within patch ----
    if (tid < K4) {
        int c  = tid / 42;               // 42 groups per channel (14 rows x 3)
        int r3 = tid - c * 42;
        int r  = r3 / 3;
        int q4 = r3 - r * 3;
        koff_s[tid] = c * HW_ + r * Wimg + q4 * 4;
    }

    // ---- per-thread A row base (2 threads per row) ----
    const int      r_t  = tid >> 1;
    const int      half = tid & 1;
    const int      cb   = half * 64;              // dst byte col base
    const uint32_t xm   = (r_t << 4) & 0x70;      // per-row swizzle mask
    int mrow = m0 + r_t;
    if (mrow >= M) mrow = M - 1;
    const float* xrow;
    {
        int n  = mrow / NV;
        int v  = mrow - n * NV;
        int p  = __ldg(valid + v);
        int gi = p / GW;
        int gj = p - gi * GW;
        xrow = x + n * CHW + gi * (PH * Wimg) + gj * PW;
    }

    // B cp.async: same row mapping, 4 x 16B per thread
    const __half* bsrc = g_Wh + (size_t)(n0 + r_t) * Kp + half * 32;

    auto issueB = [&](int kt) {
        const uint32_t bb = sb + (kt % STAGES) * STAGE_BYTES + A_BYTES + r_t * 128;
        const __half* bs = bsrc + kt * BK;
        #pragma unroll
        for (int j = 0; j < 4; ++j)
            cp16(bb + ((uint32_t)(cb + j * 16) ^ xm), bs + j * 8);
    };

    __syncthreads();   // koff table visible

    // ---- A gather helpers: chunk j (0..3) = 2 src float4 -> one STS.128 ----
    auto gld = [&](int kt2, int j, float4 gv[2]) {
        int g0 = kt2 * 16 + half * 8 + 2 * j;
        #pragma unroll
        for (int u = 0; u < 2; ++u) {
            int g = g0 + u;
            if (g < K4)
                gv[u] = __ldg(reinterpret_cast<const float4*>(xrow + koff_s[g]));
            else
                gv[u] = make_float4(0.f, 0.f, 0.f, 0.f);
        }
    };
    auto gst = [&](int kt2, int j, const float4 gv[2]) {
        const uint32_t ab = sb + (kt2 % STAGES) * STAGE_BYTES + r_t * 128;
        uint2 lo = pack4(gv[0]);
        uint2 hi = pack4(gv[1]);
        uint32_t off = (uint32_t)(cb + j * 16) ^ xm;
        asm volatile("st.shared.v4.b32 [%0], {%1,%2,%3,%4};"
                     :: "r"(ab + off), "r"(lo.x), "r"(lo.y), "r"(hi.x), "r"(hi.y)
                     : "memory");
    };

    // ---- fragment addressing: wm in {0,64}, wn in {0,32,64,96} ----
    const int wm = (wid & 1) * 64;
    const int wn = (wid >> 1) * 32;
    const int row_l = lane & 15;
    const int q_l   = lane >> 4;
    const uint32_t mask_a = (uint32_t)(((wm + row_l) << 4) & 0x70);
    const uint32_t mask_b = (uint32_t)(((wn + row_l) << 4) & 0x70);
    const uint32_t abase_t = (uint32_t)((wm + row_l) * 128);
    const uint32_t bbase_t = (uint32_t)((wn + row_l) * 128);

    float d[4][4][4];
    #pragma unroll
    for (int i = 0; i < 4; ++i)
        #pragma unroll
        for (int j = 0; j < 4; ++j)
            #pragma unroll
            for (int r = 0; r < 4; ++r)
                d[i][j][r] = 0.0f;

    // ---- prologue: gather A(0), A(1); launch B(0), B(1) ----
    {
        float4 gv[2];
        #pragma unroll
        for (int j = 0; j < 4; ++j) { gld(0, j, gv); gst(0, j, gv); }
        #pragma unroll
        for (int j = 0; j < 4; ++j) { gld(1, j, gv); gst(1, j, gv); }
    }
    issueB(0);
    asm volatile("cp.async.commit_group;" ::: "memory");
    issueB(1);
    asm volatile("cp.async.commit_group;" ::: "memory");

    uint32_t a[2][4][4];
    uint32_t b[2][2][4];

    for (int kt = 0; kt < NKT; ++kt) {
        asm volatile("cp.async.wait_group 1;" ::: "memory");
        __syncthreads();   // B(kt) + A(kt) visible; stage (kt+2)%3 free

        if (kt + 2 < NKT) issueB(kt + 2);
        asm volatile("cp.async.commit_group;" ::: "memory");
        const bool gat = (kt + 2 < NKT);
        const int  kt2 = kt + 2;

        const uint32_t astg = sb + (kt % STAGES) * STAGE_BYTES + abase_t;
        const uint32_t bstg = sb + (kt % STAGES) * STAGE_BYTES + A_BYTES + bbase_t;

        // preload s = 0 fragments
        {
            const uint32_t ca = (uint32_t)(q_l * 16) ^ mask_a;
            const uint32_t cbf = (uint32_t)(q_l * 16) ^ mask_b;
            #pragma unroll
            for (int i = 0; i < 4; ++i) ldsm_x4(a[0][i], astg + i * 2048 + ca);
            #pragma unroll
            for (int t = 0; t < 2; ++t) ldsm_x4(b[0][t], bstg + t * 2048 + cbf);
        }

        float4 gv[2];
        if (gat) gld(kt2, 0, gv);        // gather chunk 0 in flight over s=0

        #pragma unroll
        for (int s = 0; s < 4; ++s) {
            const int cur = s & 1, nxt = cur ^ 1;
            if (s < 3) {     // prefetch s+1 fragments under this step's MMAs
                const uint32_t ca  = (uint32_t)((s + 1) * 32 + q_l * 16) ^ mask_a;
                const uint32_t cbf = (uint32_t)((s + 1) * 32 + q_l * 16) ^ mask_b;
                #pragma unroll
                for (int i = 0; i < 4; ++i) ldsm_x4(a[nxt][i], astg + i * 2048 + ca);
                #pragma unroll
                for (int t = 0; t < 2; ++t) ldsm_x4(b[nxt][t], bstg + t * 2048 + cbf);
            }
            #pragma unroll
            for (int i = 0; i < 4; ++i)
                #pragma unroll
                for (int j = 0; j < 4; ++j)
                    mma_f16(d[i][j], a[cur][i],
                            b[cur][j >> 1][j & 1], b[cur][j >> 1][(j & 1) + 2]);
            // drain gather chunk s, start chunk s+1 (hides LDG under MMAs)
            if (gat) {
                gst(kt2, s, gv);
                if (s < 3) gld(kt2, s + 1, gv);
            }
        }
        // no bottom sync: top-of-next-iter sync orders stage reuse
    }

    // ---- epilogue: + bias, direct float2 stores ----
    const int g  = lane >> 2;
    const int c2 = (lane & 3) * 2;
    #pragma unroll
    for (int j = 0; j < 4; ++j) {
        const int col = n0 + wn + j * 8 + c2;
        const float2 bv = *reinterpret_cast<const float2*>(bias + col);
        #pragma unroll
        for (int i = 0; i < 4; ++i) {
            int r0 = m0 + wm + i * 16 + g;
            if (r0 < M) {
                float2 o = make_float2(d[i][j][0] + bv.x, d[i][j][1] + bv.y);
                *reinterpret_cast<float2*>(out + (size_t)r0 * E + col) = o;
            }
            int r1 = r0 + 8;
            if (r1 < M) {
                float2 o = make_float2(d[i][j][2] + bv.x, d[i][j][3] + bv.y);
                *reinterpret_cast<float2*>(out + (size_t)r1 * E + col) = o;
            }
        }
    }
}

} // namespace

extern "C" void kernel_launch(void* const* d_in, const int* in_sizes, int n_in,
                              void* d_out, int out_size) {
    const float* x     = (const float*)d_in[0];  // [96, 4, 420, 312]
    const float* Wm    = (const float*)d_in[1];  // [768, 672]
    const float* b     = (const float*)d_in[2];  // [768]
    const int*   valid = (const int*)  d_in[3];  // [390]
    float*       out   = (float*)d_out;          // [37440, 768]

    round_wh<<<(NW4 + 255) / 256, 256>>>(Wm);

    cudaFuncSetAttribute(patch_embed_gemm,
                         cudaFuncAttributeMaxDynamicSharedMemorySize, SM_TOTAL);
    patch_embed_gemm<<<MBLK * NBLK, 256, SM_TOTAL>>>(x, b, valid, out);
}

// round 15
// speedup vs baseline: 1.0463x; 1.0463x over previous
#include <cuda_runtime.h>
#include <cuda_fp16.h>
#include <cstdint>

// PatchEmbedding, fp16 tensor path, 3 kernels (split pipeline, no K padding):
//   1) round_wh: W [768,672] -> fp16 Wh (flat copy-convert)
//   2) im2col:   x gather -> fp16 Ah [37440,672], one 16B store per thread
//   3) gemm:     D = Ah * Wh^T + bias (fp32 accum). cp.async 3-stage,
//      mma.m16n8k16.f16, BM=256 x BN=128, 512 thr (16 warps, 4Mx4N),
//      warp tile 64x32, fragment double-buffering; K = 10 full 64-tiles
//      + one 32-wide tail tile (2 s-steps) -> no padded zero MMAs.

namespace {

constexpr int C_   = 4;
constexpr int Himg = 420;
constexpr int Wimg = 312;
constexpr int PH   = 14;
constexpr int PW   = 12;
constexpr int GW   = 26;
constexpr int E    = 768;
constexpr int NV   = 390;
constexpr int K    = 672;
constexpr int M    = 96 * NV;        // 37440
constexpr int HW_  = Himg * Wimg;
constexpr int CHW  = C_ * HW_;

constexpr int BM = 256, BN = 128, BK = 64;   // BK in fp16 elements (128 B)
constexpr int NKT    = 11;                   // 10 full + 1 tail (32 wide)
constexpr int NBLK   = E / BN;               // 6
constexpr int MBLK   = (M + BM - 1) / BM;    // 147
constexpr int STAGES = 3;
constexpr int A_BYTES = BM * BK * 2;               // 32 KB
constexpr int STAGE_BYTES = (BM + BN) * BK * 2;    // 48 KB
constexpr int SM_TOTAL = STAGES * STAGE_BYTES;     // 144 KB

constexpr int NW4 = E * K / 4;       // W float4 count (flat copy)
constexpr int NA2 = M * (K / 8);     // A 16B-store count (2 float4 each)

} // namespace

// scratch (module-scope device globals; allocation-free at launch time)
__device__ __align__(16) __half g_Ah[(size_t)M * K];   // ~50.3 MB
__device__ __align__(16) __half g_Wh[(size_t)E * K];   // ~1.0 MB

namespace {

__device__ __forceinline__ uint32_t smem_u32(const void* p) {
    uint32_t a;
    asm("{ .reg .u64 t; cvta.to.shared.u64 t, %1; cvt.u32.u64 %0, t; }"
        : "=r"(a) : "l"(p));
    return a;
}

__device__ __forceinline__ void cp16(uint32_t dst, const void* src) {
    asm volatile("cp.async.cg.shared.global [%0], [%1], 16;"
                 :: "r"(dst), "l"(src) : "memory");
}

__device__ __forceinline__ void ldsm_x4(uint32_t r[4], uint32_t addr) {
    asm volatile("ldmatrix.sync.aligned.m8n8.x4.shared.b16 {%0,%1,%2,%3}, [%4];"
                 : "=r"(r[0]), "=r"(r[1]), "=r"(r[2]), "=r"(r[3]) : "r"(addr));
}

__device__ __forceinline__ void mma_f16(float d[4], const uint32_t a[4],
                                        uint32_t b0, uint32_t b1) {
    asm volatile(
        "mma.sync.aligned.m16n8k16.row.col.f32.f16.f16.f32 "
        "{%0,%1,%2,%3}, {%4,%5,%6,%7}, {%8,%9}, {%0,%1,%2,%3};"
        : "+f"(d[0]), "+f"(d[1]), "+f"(d[2]), "+f"(d[3])
        : "r"(a[0]), "r"(a[1]), "r"(a[2]), "r"(a[3]), "r"(b0), "r"(b1));
}

__device__ __forceinline__ uint2 pack4(float4 v) {
    __half2 lo = __floats2half2_rn(v.x, v.y);
    __half2 hi = __floats2half2_rn(v.z, v.w);
    uint2 r;
    r.x = *reinterpret_cast<uint32_t*>(&lo);
    r.y = *reinterpret_cast<uint32_t*>(&hi);
    return r;
}

// ---- pre-pass 1: W -> fp16, flat (no padding, rows contiguous) ----
__global__ void round_wh(const float* __restrict__ Wm) {
    int idx = blockIdx.x * blockDim.x + threadIdx.x;   // float4 index
    if (idx >= NW4) return;
    uint2 val = pack4(reinterpret_cast<const float4*>(Wm)[idx]);
    *reinterpret_cast<uint2*>(g_Wh + (size_t)idx * 4) = val;
}

// ---- pre-pass 2: im2col gather -> fp16, one 16B store per thread ----
__global__ __launch_bounds__(256)
void im2col(const float* __restrict__ x, const int* __restrict__ valid) {
    int idx = blockIdx.x * blockDim.x + threadIdx.x;   // 16B-store id
    if (idx >= NA2) return;
    int m = idx / 84;                // 84 stores per row (672/8)
    int u = idx - m * 84;            // groups t0 = 2u, t1 = 2u+1

    int n  = m / NV;
    int v  = m - n * NV;
    int p  = __ldg(valid + v);
    int gi = p / GW;
    int gj = p - gi * GW;
    const float* base = x + n * CHW + gi * (PH * Wimg) + gj * PW;

    uint2 w[2];
    #pragma unroll
    for (int s = 0; s < 2; ++s) {
        int t  = 2 * u + s;          // float4-group index (0..167)
        int c  = t / 42;             // 42 groups per channel (14 rows x 3)
        int r3 = t - c * 42;
        int r  = r3 / 3;
        int q4 = r3 - r * 3;
        w[s] = pack4(*reinterpret_cast<const float4*>(
            base + c * HW_ + r * Wimg + q4 * 4));
    }
    asm volatile("st.global.v4.b32 [%0], {%1,%2,%3,%4};"
                 :: "l"(g_Ah + (size_t)m * K + u * 8),
                    "r"(w[0].x), "r"(w[0].y), "r"(w[1].x), "r"(w[1].y)
                 : "memory");
}

// ---- main GEMM: 512 threads, 16 warps (4M x 4N), warp tile 64x32 ----
__global__ __launch_bounds__(512)
void patch_embed_gemm(const float* __restrict__ bias,
                      float*       __restrict__ out)
{
    extern __shared__ char smem[];
    const uint32_t sb = smem_u32(smem);

    const int tid  = threadIdx.x;
    const int lane = tid & 31;
    const int wid  = tid >> 5;

    const int bid = blockIdx.x;
    const int n0  = (bid % NBLK) * BN;   // n innermost -> A panel L2 reuse
    const int m0  = (bid / NBLK) * BM;

    // ---- cp.async assignments ----
    const int      ar_t = tid >> 1;                 // A row 0..255
    const int      half = tid & 1;
    const int      acb  = half * 64;                // dst byte col base
    const uint32_t xma  = (ar_t << 4) & 0x70;
    const int      arow = (m0 + ar_t < M) ? (m0 + ar_t) : (M - 1);
    const __half*  asrc = g_Ah + (size_t)arow * K + half * 32;
    const int      br_t = tid >> 2;                 // B row 0..127
    const int      bq   = tid & 3;
    const int      bcb  = bq * 32;
    const uint32_t xmb  = (br_t << 4) & 0x70;
    const __half*  bsrc = g_Wh + (size_t)(n0 + br_t) * K + bq * 16;

    auto issue = [&](int kt) {
        const bool tail = (kt == NKT - 1);          // 32-wide tile
        const uint32_t st = sb + (kt % STAGES) * STAGE_BYTES;
        if (!tail || half == 0) {
            const __half* as = asrc + kt * BK;
            const uint32_t abase = st + ar_t * 128;
            #pragma unroll
            for (int j = 0; j < 4; ++j)
                cp16(abase + ((uint32_t)(acb + j * 16) ^ xma), as + j * 8);
        }
        if (!tail || bq < 2) {
            const __half* bs = bsrc + kt * BK;
            const uint32_t bbase = st + A_BYTES + br_t * 128;
            #pragma unroll
            for (int j = 0; j < 2; ++j)
                cp16(bbase + ((uint32_t)(bcb + j * 16) ^ xmb), bs + j * 8);
        }
    };

    // ---- fragment addressing: wm in {0,64,128,192}, wn in {0,32,64,96} ----
    const int wm = (wid & 3) * 64;
    const int wn = (wid >> 2) * 32;
    const int row_l = lane & 15;
    const int q_l   = lane >> 4;
    const uint32_t mask_a = (uint32_t)(((wm + row_l) << 4) & 0x70);
    const uint32_t mask_b = (uint32_t)(((wn + row_l) << 4) & 0x70);
    const uint32_t abase_t = (uint32_t)((wm + row_l) * 128);
    const uint32_t bbase_t = (uint32_t)((wn + row_l) * 128);

    float d[4][4][4];
    #pragma unroll
    for (int i = 0; i < 4; ++i)
        #pragma unroll
        for (int j = 0; j < 4; ++j)
            #pragma unroll
            for (int r = 0; r < 4; ++r)
                d[i][j][r] = 0.0f;

    issue(0);
    asm volatile("cp.async.commit_group;" ::: "memory");
    issue(1);
    asm volatile("cp.async.commit_group;" ::: "memory");

    uint32_t a[2][4][4];     // [buf][i][frag]
    uint32_t b[2][2][4];     // [buf][t][frag]

    for (int kt = 0; kt < NKT; ++kt) {
        asm volatile("cp.async.wait_group 1;" ::: "memory");
        __syncthreads();

        if (kt + 2 < NKT) issue(kt + 2);
        asm volatile("cp.async.commit_group;" ::: "memory");

        const uint32_t astg = sb + (kt % STAGES) * STAGE_BYTES + abase_t;
        const uint32_t bstg = sb + (kt % STAGES) * STAGE_BYTES + A_BYTES + bbase_t;

        // preload s = 0 fragments
        {
            const uint32_t ca = (uint32_t)(q_l * 16) ^ mask_a;
            const uint32_t cb = (uint32_t)(q_l * 16) ^ mask_b;
            #pragma unroll
            for (int i = 0; i < 4; ++i) ldsm_x4(a[0][i], astg + i * 2048 + ca);
            #pragma unroll
            for (int t = 0; t < 2; ++t) ldsm_x4(b[0][t], bstg + t * 2048 + cb);
        }

        if (kt != NKT - 1) {
            #pragma unroll
            for (int s = 0; s < 4; ++s) {
                const int cur = s & 1, nxt = cur ^ 1;
                if (s < 3) {   // prefetch s+1 fragments under this step's MMAs
                    const uint32_t ca = (uint32_t)((s + 1) * 32 + q_l * 16) ^ mask_a;
                    const uint32_t cb = (uint32_t)((s + 1) * 32 + q_l * 16) ^ mask_b;
                    #pragma unroll
                    for (int i = 0; i < 4; ++i) ldsm_x4(a[nxt][i], astg + i * 2048 + ca);
                    #pragma unroll
                    for (int t = 0; t < 2; ++t) ldsm_x4(b[nxt][t], bstg + t * 2048 + cb);
                }
                #pragma unroll
                for (int i = 0; i < 4; ++i)
                    #pragma unroll
                    for (int j = 0; j < 4; ++j)
                        mma_f16(d[i][j], a[cur][i],
                                b[cur][j >> 1][j & 1], b[cur][j >> 1][(j & 1) + 2]);
            }
        } else {
            // tail: 32-wide tile -> 2 k16 steps only
            #pragma unroll
            for (int s = 0; s < 2; ++s) {
                const int cur = s & 1, nxt = cur ^ 1;
                if (s < 1) {
                    const uint32_t ca = (uint32_t)(32 + q_l * 16) ^ mask_a;
                    const uint32_t cb = (uint32_t)(32 + q_l * 16) ^ mask_b;
                    #pragma unroll
                    for (int i = 0; i < 4; ++i) ldsm_x4(a[nxt][i], astg + i * 2048 + ca);
                    #pragma unroll
                    for (int t = 0; t < 2; ++t) ldsm_x4(b[nxt][t], bstg + t * 2048 + cb);
                }
                #pragma unroll
                for (int i = 0; i < 4; ++i)
                    #pragma unroll
                    for (int j = 0; j < 4; ++j)
                        mma_f16(d[i][j], a[cur][i],
                                b[cur][j >> 1][j & 1], b[cur][j >> 1][(j & 1) + 2]);
            }
        }
        // no bottom sync: top-of-next-iter sync orders stage reuse
    }

    // ---- epilogue: + bias, direct float2 stores ----
    const int g  = lane >> 2;
    const int c2 = (lane & 3) * 2;
    #pragma unroll
    for (int j = 0; j < 4; ++j) {
        const int col = n0 + wn + j * 8 + c2;
        const float2 bv = *reinterpret_cast<const float2*>(bias + col);
        #pragma unroll
        for (int i = 0; i < 4; ++i) {
            int r0 = m0 + wm + i * 16 + g;
            if (r0 < M) {
                float2 o = make_float2(d[i][j][0] + bv.x, d[i][j][1] + bv.y);
                *reinterpret_cast<float2*>(out + (size_t)r0 * E + col) = o;
            }
            int r1 = r0 + 8;
            if (r1 < M) {
                float2 o = make_float2(d[i][j][2] + bv.x, d[i][j][3] + bv.y);
                *reinterpret_cast<float2*>(out + (size_t)r1 * E + col) = o;
            }
        }
    }
}

} // namespace

extern "C" void kernel_launch(void* const* d_in, const int* in_sizes, int n_in,
                              void* d_out, int out_size) {
    const float* x     = (const float*)d_in[0];  // [96, 4, 420, 312]
    const float* Wm    = (const float*)d_in[1];  // [768, 672]
    const float* b     = (const float*)d_in[2];  // [768]
    const int*   valid = (const int*)  d_in[3];  // [390]
    float*       out   = (float*)d_out;          // [37440, 768]

    round_wh<<<(NW4 + 255) / 256, 256>>>(Wm);
    im2col<<<(NA2 + 255) / 256, 256>>>(x, valid);

    cudaFuncSetAttribute(patch_embed_gemm,
                         cudaFuncAttributeMaxDynamicSharedMemorySize, SM_TOTAL);
    patch_embed_gemm<<<MBLK * NBLK, 512, SM_TOTAL>>>(b, out);
}

// round 16
// speedup vs baseline: 1.0740x; 1.0265x over previous
#include <cuda_runtime.h>
#include <cuda_fp16.h>
#include <cstdint>

// PatchEmbedding, fp16 tensor path, 2 kernels:
//   1) round_wh: W -> fp16 Wh [768,704] (padded); also zeroes panel counters.
//   2) gemm: each A-panel (256 rows) is gathered cooperatively by the 6 CTAs
//      that consume it (rows nb, nb+6, ... -> g_Ah, fp16, padded), gated by a
//      per-panel arrival counter, then the proven cp.async 3-stage
//      mma.m16n8k16.f16 GEMM runs: BM=256 x BN=128, 512 thr (16 warps, 4Mx4N),
//      warp tile 64x32, fragment double-buffering. D = A*W^T + bias.

namespace {

constexpr int C_   = 4;
constexpr int Himg = 420;
constexpr int Wimg = 312;
constexpr int PH   = 14;
constexpr int PW   = 12;
constexpr int GW   = 26;
constexpr int E    = 768;
constexpr int NV   = 390;
constexpr int K    = 672;
constexpr int Kp   = 704;            // padded K (multiple of 64)
constexpr int Kp4  = Kp / 4;         // 176 half4-groups per row
constexpr int K4   = K / 4;          // 168 valid groups
constexpr int M    = 96 * NV;        // 37440
constexpr int HW_  = Himg * Wimg;
constexpr int CHW  = C_ * HW_;

constexpr int BM = 256, BN = 128, BK = 64;   // BK in fp16 elements (128 B)
constexpr int NKT    = Kp / BK;              // 11
constexpr int NBLK   = E / BN;               // 6
constexpr int MBLK   = (M + BM - 1) / BM;    // 147 panels
constexpr int STAGES = 3;
constexpr int A_BYTES = BM * BK * 2;               // 32 KB
constexpr int STAGE_BYTES = (BM + BN) * BK * 2;    // 48 KB
constexpr int SM_TOTAL = STAGES * STAGE_BYTES;     // 144 KB

constexpr int NW4 = E * Kp4;         // W half4-groups

} // namespace

// scratch (module-scope device globals; allocation-free at launch time)
__device__ __align__(16) __half g_Ah[(size_t)M * Kp];   // ~52.7 MB
__device__ __align__(16) __half g_Wh[(size_t)E * Kp];   // ~1.1 MB
__device__ int g_cnt[MBLK];                             // panel arrival counters

namespace {

__device__ __forceinline__ uint32_t smem_u32(const void* p) {
    uint32_t a;
    asm("{ .reg .u64 t; cvta.to.shared.u64 t, %1; cvt.u32.u64 %0, t; }"
        : "=r"(a) : "l"(p));
    return a;
}

__device__ __forceinline__ void cp16(uint32_t dst, const void* src) {
    asm volatile("cp.async.cg.shared.global [%0], [%1], 16;"
                 :: "r"(dst), "l"(src) : "memory");
}

__device__ __forceinline__ void ldsm_x4(uint32_t r[4], uint32_t addr) {
    asm volatile("ldmatrix.sync.aligned.m8n8.x4.shared.b16 {%0,%1,%2,%3}, [%4];"
                 : "=r"(r[0]), "=r"(r[1]), "=r"(r[2]), "=r"(r[3]) : "r"(addr));
}

__device__ __forceinline__ void mma_f16(float d[4], const uint32_t a[4],
                                        uint32_t b0, uint32_t b1) {
    asm volatile(
        "mma.sync.aligned.m16n8k16.row.col.f32.f16.f16.f32 "
        "{%0,%1,%2,%3}, {%4,%5,%6,%7}, {%8,%9}, {%0,%1,%2,%3};"
        : "+f"(d[0]), "+f"(d[1]), "+f"(d[2]), "+f"(d[3])
        : "r"(a[0]), "r"(a[1]), "r"(a[2]), "r"(a[3]), "r"(b0), "r"(b1));
}

__device__ __forceinline__ uint2 pack4(float4 v) {
    __half2 lo = __floats2half2_rn(v.x, v.y);
    __half2 hi = __floats2half2_rn(v.z, v.w);
    uint2 r;
    r.x = *reinterpret_cast<uint32_t*>(&lo);
    r.y = *reinterpret_cast<uint32_t*>(&hi);
    return r;
}

// ---- pre-pass: W -> fp16 padded; zero panel counters ----
__global__ void round_wh(const float* __restrict__ Wm) {
    int idx = blockIdx.x * blockDim.x + threadIdx.x;   // half4-group id
    if (idx < MBLK) g_cnt[idx] = 0;
    if (idx >= NW4) return;
    int e = idx / Kp4;
    int t = idx - e * Kp4;
    uint2 val = make_uint2(0, 0);
    if (t < K4)
        val = pack4(*reinterpret_cast<const float4*>(Wm + (size_t)e * K + t * 4));
    *reinterpret_cast<uint2*>(g_Wh + (size_t)e * Kp + t * 4) = val;
}

// ---- fused GEMM: gather own panel slice, gate, then 3-stage pipeline ----
__global__ __launch_bounds__(512)
void patch_embed_gemm(const float* __restrict__ x,
                      const float* __restrict__ bias,
                      const int*   __restrict__ valid,
                      float*       __restrict__ out)
{
    extern __shared__ char smem[];
    const uint32_t sb = smem_u32(smem);

    const int tid  = threadIdx.x;
    const int lane = tid & 31;
    const int wid  = tid >> 5;

    const int bid   = blockIdx.x;
    const int nb    = bid % NBLK;        // n-block (innermost -> L2 reuse)
    const int panel = bid / NBLK;
    const int n0    = nb * BN;
    const int m0    = panel * BM;

    // ================= producer: gather rows nb, nb+6, ... of this panel ====
    for (int k = wid; ; k += 16) {
        int rr = nb + 6 * k;             // row within panel
        if (rr >= BM) break;
        int m = m0 + rr;
        if (m >= M) break;
        int n  = m / NV;
        int v  = m - n * NV;
        int p  = __ldg(valid + v);
        int gi = p / GW;
        int gj = p - gi * GW;
        const float* xrow = x + n * CHW + gi * (PH * Wimg) + gj * PW;
        __half* dst = g_Ah + (size_t)m * Kp;
        #pragma unroll
        for (int g = lane; g < Kp4; g += 32) {
            uint2 w = make_uint2(0, 0);
            if (g < K4) {
                int c  = g / 42;         // 42 groups per channel (14 rows x 3)
                int r3 = g - c * 42;
                int r  = r3 / 3;
                int q4 = r3 - r * 3;
                w = pack4(*reinterpret_cast<const float4*>(
                    xrow + c * HW_ + r * Wimg + q4 * 4));
            }
            *reinterpret_cast<uint2*>(dst + g * 4) = w;
        }
    }
    __syncthreads();
    if (tid == 0) {
        __threadfence();                             // release slice writes
        atomicAdd(&g_cnt[panel], 1);
        while (*(volatile int*)&g_cnt[panel] < NBLK) // wait for all 6 producers
            __nanosleep(64);
        __threadfence();                             // acquire peer writes
    }
    __syncthreads();

    // ================= consumer: proven 3-stage cp.async GEMM ===============
    const int      ar_t = tid >> 1;
    const int      acb  = (tid & 1) * 64;
    const uint32_t xma  = (ar_t << 4) & 0x70;
    const int      arow = (m0 + ar_t < M) ? (m0 + ar_t) : (M - 1);
    const __half*  asrc = g_Ah + (size_t)arow * Kp + (tid & 1) * 32;
    const int      br_t = tid >> 2;
    const int      bcb  = (tid & 3) * 32;
    const uint32_t xmb  = (br_t << 4) & 0x70;
    const __half*  bsrc = g_Wh + (size_t)(n0 + br_t) * Kp + (tid & 3) * 16;

    auto issue = [&](int kt) {
        const uint32_t st = sb + (kt % STAGES) * STAGE_BYTES;
        const __half* as = asrc + kt * BK;
        const __half* bs = bsrc + kt * BK;
        const uint32_t abase = st + ar_t * 128;
        #pragma unroll
        for (int j = 0; j < 4; ++j)
            cp16(abase + ((uint32_t)(acb + j * 16) ^ xma), as + j * 8);
        const uint32_t bbase = st + A_BYTES + br_t * 128;
        #pragma unroll
        for (int j = 0; j < 2; ++j)
            cp16(bbase + ((uint32_t)(bcb + j * 16) ^ xmb), bs + j * 8);
    };

    const int wm = (wid & 3) * 64;
    const int wn = (wid >> 2) * 32;
    const int row_l = lane & 15;
    const int q_l   = lane >> 4;
    const uint32_t mask_a = (uint32_t)(((wm + row_l) << 4) & 0x70);
    const uint32_t mask_b = (uint32_t)(((wn + row_l) << 4) & 0x70);
    const uint32_t abase_t = (uint32_t)((wm + row_l) * 128);
    const uint32_t bbase_t = (uint32_t)((wn + row_l) * 128);

    float d[4][4][4];
    #pragma unroll
    for (int i = 0; i < 4; ++i)
        #pragma unroll
        for (int j = 0; j < 4; ++j)
            #pragma unroll
            for (int r = 0; r < 4; ++r)
                d[i][j][r] = 0.0f;

    issue(0);
    asm volatile("cp.async.commit_group;" ::: "memory");
    issue(1);
    asm volatile("cp.async.commit_group;" ::: "memory");

    uint32_t a[2][4][4];
    uint32_t b[2][2][4];

    for (int kt = 0; kt < NKT; ++kt) {
        asm volatile("cp.async.wait_group 1;" ::: "memory");
        __syncthreads();

        if (kt + 2 < NKT) issue(kt + 2);
        asm volatile("cp.async.commit_group;" ::: "memory");

        const uint32_t astg = sb + (kt % STAGES) * STAGE_BYTES + abase_t;
        const uint32_t bstg = sb + (kt % STAGES) * STAGE_BYTES + A_BYTES + bbase_t;

        // preload s = 0 fragments
        {
            const uint32_t ca = (uint32_t)(q_l * 16) ^ mask_a;
            const uint32_t cb = (uint32_t)(q_l * 16) ^ mask_b;
            #pragma unroll
            for (int i = 0; i < 4; ++i) ldsm_x4(a[0][i], astg + i * 2048 + ca);
            #pragma unroll
            for (int t = 0; t < 2; ++t) ldsm_x4(b[0][t], bstg + t * 2048 + cb);
        }

        #pragma unroll
        for (int s = 0; s < 4; ++s) {
            const int cur = s & 1, nxt = cur ^ 1;
            if (s < 3) {       // prefetch s+1 fragments under this step's MMAs
                const uint32_t ca = (uint32_t)((s + 1) * 32 + q_l * 16) ^ mask_a;
                const uint32_t cb = (uint32_t)((s + 1) * 32 + q_l * 16) ^ mask_b;
                #pragma unroll
                for (int i = 0; i < 4; ++i) ldsm_x4(a[nxt][i], astg + i * 2048 + ca);
                #pragma unroll
                for (int t = 0; t < 2; ++t) ldsm_x4(b[nxt][t], bstg + t * 2048 + cb);
            }
            #pragma unroll
            for (int i = 0; i < 4; ++i)
                #pragma unroll
                for (int j = 0; j < 4; ++j)
                    mma_f16(d[i][j], a[cur][i],
                            b[cur][j >> 1][j & 1], b[cur][j >> 1][(j & 1) + 2]);
        }
        // no bottom sync: top-of-next-iter sync orders stage reuse
    }

    // ---- epilogue: + bias, direct float2 stores ----
    const int g  = lane >> 2;
    const int c2 = (lane & 3) * 2;
    #pragma unroll
    for (int j = 0; j < 4; ++j) {
        const int col = n0 + wn + j * 8 + c2;
        const float2 bv = *reinterpret_cast<const float2*>(bias + col);
        #pragma unroll
        for (int i = 0; i < 4; ++i) {
            int r0 = m0 + wm + i * 16 + g;
            if (r0 < M) {
                float2 o = make_float2(d[i][j][0] + bv.x, d[i][j][1] + bv.y);
                *reinterpret_cast<float2*>(out + (size_t)r0 * E + col) = o;
            }
            int r1 = r0 + 8;
            if (r1 < M) {
                float2 o = make_float2(d[i][j][2] + bv.x, d[i][j][3] + bv.y);
                *reinterpret_cast<float2*>(out + (size_t)r1 * E + col) = o;
            }
        }
    }
}

} // namespace

extern "C" void kernel_launch(void* const* d_in, const int* in_sizes, int n_in,
                              void* d_out, int out_size) {
    const float* x     = (const float*)d_in[0];  // [96, 4, 420, 312]
    const float* Wm    = (const float*)d_in[1];  // [768, 672]
    const float* b     = (const float*)d_in[2];  // [768]
    const int*   valid = (const int*)  d_in[3];  // [390]
    float*       out   = (float*)d_out;          // [37440, 768]

    round_wh<<<(NW4 + 255) / 256, 256>>>(Wm);

    cudaFuncSetAttribute(patch_embed_gemm,
                         cudaFuncAttributeMaxDynamicSharedMemorySize, SM_TOTAL);
    patch_embed_gemm<<<MBLK * NBLK, 512, SM_TOTAL>>>(x, b, valid, out);
}